// round 6
// baseline (speedup 1.0000x reference)
#include <cuda_runtime.h>
#include <cuda_bf16.h>
#include <cstdint>

// Problem constants (fixed by the dataset)
#define BB 32      // batch
#define LL 128     // sequence length
#define TT 63      // tree nodes (2^6 - 1)
#define EE 128     // embedding dim
#define CC 128     // conv/encoder channels
#define HH 256     // GRU hidden
#define GG 768     // 3*H gate columns

// ---------------------------------------------------------------------------
// Packed fp32x2 helpers (bitwise-identical fp32 rounding per lane)
// ---------------------------------------------------------------------------
__device__ __forceinline__ unsigned long long fma2(unsigned long long a,
                                                   unsigned long long b,
                                                   unsigned long long c) {
    unsigned long long d;
    asm("fma.rn.f32x2 %0, %1, %2, %3;" : "=l"(d) : "l"(a), "l"(b), "l"(c));
    return d;
}
__device__ __forceinline__ unsigned long long pk2(float v) {   // {v, v}
    unsigned long long r;
    asm("mov.b64 %0, {%1, %1};" : "=l"(r) : "f"(v));
    return r;
}
__device__ __forceinline__ float2 upk(unsigned long long v) {
    float2 f;
    asm("mov.b64 {%0, %1}, %2;" : "=f"(f.x), "=f"(f.y) : "l"(v));
    return f;
}

// ---------------------------------------------------------------------------
// Device scratch (static allocations only — no cudaMalloc allowed)
// ---------------------------------------------------------------------------
__device__ float d_WcT[EE * CC];            // [e][c]  (Wc transposed)
__device__ float d_WihT0[CC * GG];          // [k][g]  forward  Wih^T
__device__ float d_WihT1[CC * GG];          // [k][g]  backward Wih^T
__device__ float d_enc[BB * LL * CC];       // encoder output (b*L+l, c)
__device__ float d_gi0[(long)BB * LL * GG]; // precomputed input gates, fwd
__device__ float d_gi1[(long)BB * LL * GG]; // precomputed input gates, bwd

// ---------------------------------------------------------------------------
// Setup: transpose weights.
// ---------------------------------------------------------------------------
__global__ void k_setup(const float* __restrict__ Wc,
                        const float* __restrict__ Wih_f,
                        const float* __restrict__ Wih_b)
{
    const int i      = blockIdx.x * blockDim.x + threadIdx.x;
    const int stride = gridDim.x * blockDim.x;

    for (int idx = i; idx < EE * CC; idx += stride) {
        int e = idx / CC, c = idx % CC;
        d_WcT[e * CC + c] = Wc[c * EE + e];
    }
    for (int idx = i; idx < CC * GG; idx += stride) {
        int k = idx / GG, g = idx % GG;
        d_WihT0[idx] = Wih_f[g * CC + k];
        d_WihT1[idx] = Wih_b[g * CC + k];
    }
}

// ---------------------------------------------------------------------------
// K1 v3: fused tree encoder. One CTA per (b,l), 256 threads, 2 CTAs/SM
// (register-capped to 128 via launch_bounds; only 4 e-vectors live at once,
//  wu[4] loaded once per k-quad and reused across both 4-node groups).
// Shared (floats): ws[128*128] @0, es[64*128] @16384 (doubles as node buf),
//                  bcs[128] @24576, tks[64] @24704
// ---------------------------------------------------------------------------
#define K1_WS 0
#define K1_ES 16384
#define K1_BC 24576
#define K1_TK 24704
#define K1_SMEM_FLOATS 24768

__global__ void __launch_bounds__(256, 2) k_tree_encode(const int* __restrict__ tokens,
                                                        const float* __restrict__ emb,
                                                        const float* __restrict__ bc)
{
    extern __shared__ float sm[];
    float* ws  = sm + K1_WS;
    float* es  = sm + K1_ES;
    float* bcs = sm + K1_BC;
    int*   tks = (int*)(sm + K1_TK);

    const int bl  = blockIdx.x;
    const int tid = threadIdx.x;

    if (tid < TT) tks[tid] = tokens[bl * TT + tid];
    if (tid < CC) bcs[tid] = bc[tid];

    for (int idx = tid; idx < (EE * CC) / 4; idx += 256)
        ((float4*)ws)[idx] = ((const float4*)d_WcT)[idx];
    __syncthreads();   // tks ready

    for (int idx = tid; idx < (64 * EE) / 4; idx += 256) {
        int t  = idx >> 5;
        int c4 = (idx & 31) << 2;
        float4 v = make_float4(0.f, 0.f, 0.f, 0.f);
        if (t < TT) v = *(const float4*)&emb[(long)tks[t] * EE + c4];
        *(float4*)&es[t * 128 + c4] = v;
    }
    __syncthreads();

    const int w     = tid >> 5;
    const int lane  = tid & 31;
    const int c4    = lane << 2;
    const int tbase = w * 8;

    unsigned long long acc2[8][2];
    #pragma unroll
    for (int n = 0; n < 8; n++) { acc2[n][0] = 0ull; acc2[n][1] = 0ull; }

    for (int k = 0; k < EE; k += 4) {
        ulonglong2 wu[4];
        #pragma unroll
        for (int kk = 0; kk < 4; kk++)
            wu[kk] = *(const ulonglong2*)&ws[(k + kk) * 128 + c4];

        #pragma unroll
        for (int g = 0; g < 2; g++) {
            float4 e4[4];
            #pragma unroll
            for (int n = 0; n < 4; n++)
                e4[n] = *(float4*)&es[(tbase + g * 4 + n) * 128 + k];
            #pragma unroll
            for (int kk = 0; kk < 4; kk++) {
                #pragma unroll
                for (int n = 0; n < 4; n++) {
                    float ev = (kk == 0) ? e4[n].x : (kk == 1) ? e4[n].y
                             : (kk == 2) ? e4[n].z : e4[n].w;
                    unsigned long long eb = pk2(ev);
                    acc2[g * 4 + n][0] = fma2(eb, wu[kk].x, acc2[g * 4 + n][0]);
                    acc2[g * 4 + n][1] = fma2(eb, wu[kk].y, acc2[g * 4 + n][1]);
                }
            }
        }
    }

    // in-place store: this warp owns rows [tbase, tbase+8)
    {
        float4 bcv = *(float4*)&bcs[c4];
        #pragma unroll
        for (int n = 0; n < 8; n++) {
            int t = tbase + n;
            if (t < TT) {
                float2 lo = upk(acc2[n][0]);
                float2 hi = upk(acc2[n][1]);
                float4 r;
                r.x = lo.x + bcv.x;
                r.y = lo.y + bcv.y;
                r.z = hi.x + bcv.z;
                r.w = hi.y + bcv.w;
                *(float4*)&es[t * 128 + c4] = r;
            }
        }
    }
    __syncthreads();

    // heap accumulation + max + relu (per-channel)
    if (tid < CC) {
        const int c = tid;
        float m = -3.0e38f;
        #pragma unroll
        for (int t = TT - 1; t >= 31; t--) m = fmaxf(m, es[t * 128 + c]);
        #pragma unroll
        for (int t = 30; t >= 0; t--) {
            float v = es[t * 128 + c] + es[(2 * t + 1) * 128 + c] + es[(2 * t + 2) * 128 + c];
            es[t * 128 + c] = v;
            m = fmaxf(m, v);
        }
        d_enc[bl * CC + c] = fmaxf(m, 0.f);
    }
}

// ---------------------------------------------------------------------------
// K2 v3: gi[d] = enc @ Wih[d]^T + bih[d] — same reg-capped structure.
// Shared: ws[128*128] @0, es[64*128] @16384, bis[128] @24576
// ---------------------------------------------------------------------------
#define K2_WS 0
#define K2_ES 16384
#define K2_BI 24576
#define K2_SMEM_FLOATS 24704

__global__ void __launch_bounds__(256, 2) k_gi(const float* __restrict__ bih_f,
                                               const float* __restrict__ bih_b)
{
    extern __shared__ float sm[];
    float* ws  = sm + K2_WS;
    float* es  = sm + K2_ES;
    float* bis = sm + K2_BI;

    const int mt = blockIdx.x;
    const int nt = blockIdx.y;
    const int d  = blockIdx.z;
    const int m0 = mt * 64;
    const int g0 = nt * 128;
    const int tid = threadIdx.x;

    const float* WT  = d ? d_WihT1 : d_WihT0;
    const float* bih = d ? bih_b   : bih_f;
    float*       gi  = d ? d_gi1   : d_gi0;

    for (int idx = tid; idx < (128 * 128) / 4; idx += 256) {
        int k  = idx >> 5;
        int j4 = (idx & 31) << 2;
        float4 v = *(const float4*)&WT[k * GG + g0 + j4];
        *(float4*)&ws[k * 128 + j4] = v;
    }
    for (int idx = tid; idx < (64 * 128) / 4; idx += 256) {
        int i  = idx >> 5;
        int k4 = (idx & 31) << 2;
        float4 v = *(const float4*)&d_enc[(m0 + i) * CC + k4];
        *(float4*)&es[i * 128 + k4] = v;
    }
    if (tid < 128) bis[tid] = bih[g0 + tid];
    __syncthreads();

    const int w     = tid >> 5;
    const int lane  = tid & 31;
    const int c4    = lane << 2;
    const int ibase = w * 8;

    unsigned long long acc2[8][2];
    #pragma unroll
    for (int n = 0; n < 8; n++) { acc2[n][0] = 0ull; acc2[n][1] = 0ull; }

    for (int k = 0; k < CC; k += 4) {
        ulonglong2 wu[4];
        #pragma unroll
        for (int kk = 0; kk < 4; kk++)
            wu[kk] = *(const ulonglong2*)&ws[(k + kk) * 128 + c4];

        #pragma unroll
        for (int g = 0; g < 2; g++) {
            float4 e4[4];
            #pragma unroll
            for (int n = 0; n < 4; n++)
                e4[n] = *(float4*)&es[(ibase + g * 4 + n) * 128 + k];
            #pragma unroll
            for (int kk = 0; kk < 4; kk++) {
                #pragma unroll
                for (int n = 0; n < 4; n++) {
                    float ev = (kk == 0) ? e4[n].x : (kk == 1) ? e4[n].y
                             : (kk == 2) ? e4[n].z : e4[n].w;
                    unsigned long long eb = pk2(ev);
                    acc2[g * 4 + n][0] = fma2(eb, wu[kk].x, acc2[g * 4 + n][0]);
                    acc2[g * 4 + n][1] = fma2(eb, wu[kk].y, acc2[g * 4 + n][1]);
                }
            }
        }
    }

    float4 bv = *(float4*)&bis[c4];
    #pragma unroll
    for (int n = 0; n < 8; n++) {
        float2 lo = upk(acc2[n][0]);
        float2 hi = upk(acc2[n][1]);
        float4 r;
        r.x = lo.x + bv.x;
        r.y = lo.y + bv.y;
        r.z = hi.x + bv.z;
        r.w = hi.y + bv.w;
        *(float4*)&gi[(long)(m0 + ibase + n) * GG + g0 + c4] = r;
    }
}

// ---------------------------------------------------------------------------
// K3 v5: cluster GRU with point-to-point mbarrier sync (no cluster.sync in
// the step loop, no CCTL.IVALL L1 flush, vectorized DSMEM h push).
// Round r (pushes during step r) uses mbar[r&1]; step st waits round st-1
// on mbar[(st-1)&1], phase parity ((st-1)>>1)&1. 48 push threads per CTA:
// 3 peers x 16 chunks of 8 floats (2x st.v4 + 1 release-arrive each).
// ---------------------------------------------------------------------------
__device__ __forceinline__ uint32_t smem_u32(const void* p) {
    uint32_t a;
    asm("{ .reg .u64 t; cvta.to.shared.u64 t, %1; cvt.u32.u64 %0, t; }"
        : "=r"(a) : "l"(p));
    return a;
}

__device__ __forceinline__ void push2_arrive(uint32_t laddr, uint32_t rank,
                                             float4 v0, float4 v1, uint32_t mbar_l) {
    asm volatile(
        "{\n\t"
        ".reg .b32 ra, rb;\n\t"
        "mapa.shared::cluster.u32 ra, %0, %1;\n\t"
        "mapa.shared::cluster.u32 rb, %10, %1;\n\t"
        "st.shared::cluster.v4.f32 [ra], {%2, %3, %4, %5};\n\t"
        "st.shared::cluster.v4.f32 [ra+16], {%6, %7, %8, %9};\n\t"
        "mbarrier.arrive.release.cluster.shared::cluster.b64 _, [rb];\n\t"
        "}"
        :: "r"(laddr), "r"(rank),
           "f"(v0.x), "f"(v0.y), "f"(v0.z), "f"(v0.w),
           "f"(v1.x), "f"(v1.y), "f"(v1.z), "f"(v1.w),
           "r"(mbar_l) : "memory");
}

__device__ __forceinline__ void waitparity_cluster(uint32_t mbar, uint32_t parity) {
    asm volatile(
        "{\n\t"
        ".reg .pred P;\n\t"
        "WL_%=:\n\t"
        "mbarrier.try_wait.parity.acquire.cluster.shared::cta.b64 P, [%0], %1, 0x989680;\n\t"
        "@P bra WD_%=;\n\t"
        "bra WL_%=;\n\t"
        "WD_%=:\n\t"
        "}"
        :: "r"(mbar), "r"(parity) : "memory");
}

__global__ void __launch_bounds__(384, 1) __cluster_dims__(4, 1, 1)
k_gru(const float* __restrict__ Whh_f, const float* __restrict__ bhh_f,
      const float* __restrict__ Whh_b, const float* __restrict__ bhh_b,
      float* __restrict__ out)
{
    __shared__ float hbuf[2][2][HH];     // [buf][bt][unit]
    __shared__ float part[2][2][192];    // [half][bt][row] partial dots
    __shared__ unsigned long long mbar[2];

    const int tid = threadIdx.x;
    uint32_t cr;
    asm("mov.u32 %0, %%cluster_ctarank;" : "=r"(cr));

    const int cid = blockIdx.x >> 2;
    const int d   = cid >> 4;
    const int bp  = cid & 15;
    const int U0  = (int)cr << 6;

    const float* Whh = d ? Whh_b : Whh_f;
    const float* bhh = d ? bhh_b : bhh_f;
    const float* gi  = d ? d_gi1 : d_gi0;

    const int w    = tid >> 5;
    const int lane = tid & 31;
    const int rw   = (w % 6) * 32 + lane;  // 0..191  (gate*64 + u)
    const int half = w / 6;                // 0 or 1

    const int gate = rw >> 6, uu = rw & 63;
    float4 wreg[32];
    {
        const float* wrow = &Whh[(gate * HH + U0 + uu) * HH + half * 128];
        #pragma unroll
        for (int i = 0; i < 32; i++) wreg[i] = *(const float4*)&wrow[i * 4];
    }

    const int u_f   = tid & 63;
    const int bt_f  = tid >> 6;
    const int bglob = bp * 2 + bt_f;
    float br = 0.f, bz = 0.f, bn = 0.f;
    if (tid < 128) {
        br = bhh[U0 + u_f];
        bz = bhh[HH + U0 + u_f];
        bn = bhh[2 * HH + U0 + u_f];
    }

    // push-thread constants (tid in [128,176): 3 peers x 16 chunks of 8 floats)
    const int  pidx  = tid - 128;
    const uint32_t prk = (cr + 1 + (uint32_t)(pidx >> 4)) & 3;
    const int  pch   = pidx & 15;
    const int  pbt   = pch >> 3;
    const int  poff  = (pch & 7) << 3;   // float offset within this CTA's 64 units

    for (int i = tid; i < 2 * HH; i += 384) hbuf[0][i >> 8][i & 255] = 0.f;
    if (tid == 0) {
        asm volatile("mbarrier.init.shared.b64 [%0], %1;"
                     :: "r"(smem_u32(&mbar[0])), "r"(48) : "memory");
        asm volatile("mbarrier.init.shared.b64 [%0], %1;"
                     :: "r"(smem_u32(&mbar[1])), "r"(48) : "memory");
    }
    __syncthreads();

    // all peers' mbarriers + h0 ready before any DSMEM traffic
    asm volatile("barrier.cluster.arrive.aligned;" ::: "memory");
    asm volatile("barrier.cluster.wait.aligned;"   ::: "memory");

    const uint32_t mb[2] = { smem_u32(&mbar[0]), smem_u32(&mbar[1]) };

    float mx = -3.0e38f;

    for (int st = 0; st < LL; st++) {
        const int p = st & 1;
        const int t = d ? (LL - 1 - st) : st;

        // gi prefetch (independent of h — issue before the wait)
        float gir = 0.f, giz = 0.f, gin = 0.f;
        if (tid < 128) {
            const long gb = ((long)bglob * LL + t) * GG + U0 + u_f;
            gir = __ldg(&gi[gb]);
            giz = __ldg(&gi[gb + HH]);
            gin = __ldg(&gi[gb + 2 * HH]);
        }

        // wait for round st-1 (peers' h_st pushes)
        if (st > 0) {
            const int r = st - 1;
            waitparity_cluster(mb[r & 1], (uint32_t)((r >> 1) & 1));
        }

        // dot products: h loads are warp-broadcast LDS, weights in registers
        float4 a0 = make_float4(0.f, 0.f, 0.f, 0.f);
        float4 a1 = make_float4(0.f, 0.f, 0.f, 0.f);
        {
            const float* h0 = &hbuf[p][0][half * 128];
            const float* h1 = &hbuf[p][1][half * 128];
            #pragma unroll
            for (int i = 0; i < 32; i++) {
                float4 wv = wreg[i];
                float4 x0 = *(const float4*)&h0[i * 4];
                float4 x1 = *(const float4*)&h1[i * 4];
                a0.x += wv.x * x0.x; a0.y += wv.y * x0.y;
                a0.z += wv.z * x0.z; a0.w += wv.w * x0.w;
                a1.x += wv.x * x1.x; a1.y += wv.y * x1.y;
                a1.z += wv.z * x1.z; a1.w += wv.w * x1.w;
            }
        }
        const float s0 = (a0.x + a0.y) + (a0.z + a0.w);
        const float s1 = (a1.x + a1.y) + (a1.z + a1.w);

        part[half][0][rw] = s0;
        part[half][1][rw] = s1;
        __syncthreads();

        // finalize: sum halves, GRU nonlinearity, write local h
        if (tid < 128) {
            const float gr = part[0][bt_f][u_f]       + part[1][bt_f][u_f];
            const float gz = part[0][bt_f][64 + u_f]  + part[1][bt_f][64 + u_f];
            const float gn = part[0][bt_f][128 + u_f] + part[1][bt_f][128 + u_f];
            const float hp = hbuf[p][bt_f][U0 + u_f];

            const float r  = 1.f / (1.f + __expf(-(gir + gr + br)));
            const float z  = 1.f / (1.f + __expf(-(giz + gz + bz)));
            const float nn = tanhf(gin + r * (gn + bn));
            const float hn = (1.f - z) * nn + z * hp;
            mx = fmaxf(mx, hn);

            hbuf[p ^ 1][bt_f][U0 + u_f] = hn;
        }
        __syncthreads();

        // push round st: vectorized DSMEM copy of this CTA's 128 new h values
        if (st < LL - 1 && (unsigned)pidx < 48u) {
            float* src = &hbuf[p ^ 1][pbt][U0 + poff];
            float4 v0 = *(float4*)src;
            float4 v1 = *(float4*)(src + 4);
            push2_arrive(smem_u32(src), prk, v0, v1, mb[st & 1]);
        }
    }

    if (tid < 128) out[bglob * 512 + d * 256 + U0 + u_f] = mx;

    // keep smem alive until all cluster traffic definitely drained
    asm volatile("barrier.cluster.arrive.aligned;" ::: "memory");
    asm volatile("barrier.cluster.wait.aligned;"   ::: "memory");
}

// ---------------------------------------------------------------------------
// kernel_launch
// ---------------------------------------------------------------------------
extern "C" void kernel_launch(void* const* d_in, const int* in_sizes, int n_in,
                              void* d_out, int out_size)
{
    const int*   tokens = (const int*)  d_in[0];
    const float* emb    = (const float*)d_in[1];
    const float* Wc     = (const float*)d_in[2];
    const float* bc     = (const float*)d_in[3];
    const float* Wih_f  = (const float*)d_in[4];
    const float* Whh_f  = (const float*)d_in[5];
    const float* bih_f  = (const float*)d_in[6];
    const float* bhh_f  = (const float*)d_in[7];
    const float* Wih_b  = (const float*)d_in[8];
    const float* Whh_b  = (const float*)d_in[9];
    const float* bih_b  = (const float*)d_in[10];
    const float* bhh_b  = (const float*)d_in[11];
    float* out = (float*)d_out;

    const int SM1 = K1_SMEM_FLOATS * 4;
    const int SM2 = K2_SMEM_FLOATS * 4;

    cudaFuncSetAttribute(k_tree_encode, cudaFuncAttributeMaxDynamicSharedMemorySize, SM1);
    cudaFuncSetAttribute(k_gi,          cudaFuncAttributeMaxDynamicSharedMemorySize, SM2);

    k_setup<<<128, 256>>>(Wc, Wih_f, Wih_b);
    k_tree_encode<<<BB * LL, 256, SM1>>>(tokens, emb, bc);
    dim3 g2(64, 6, 2);
    k_gi<<<g2, 256, SM2>>>(bih_f, bih_b);
    k_gru<<<128, 384>>>(Whh_f, bhh_f, Whh_b, bhh_b, out);
}